// round 3
// baseline (speedup 1.0000x reference)
#include <cuda_runtime.h>
#include <cuda_bf16.h>

// Idx2PixelLayer: bilinear gather from visible[2048,2048,8] at 1e6 coords.
//
// R2: L2 policy hints, fixed for sm_103a ptxas (evict_last requires v8.b32).
//  - table gathers: ld.global.nc.L2::evict_last.v8.b32 (32B per load; the two
//    column-adjacent pixels per row are one 64B chunk -> 2 loads/row, 4 total)
//  - coords: __ldcs (streaming), output: __stcs (streaming)

static constexpr int HW    = 2048;
static constexpr int CH    = 8;
static constexpr float MODV = 2044.0f;   // H - 4
static constexpr float DIMF = 2048.0f;

struct F8 { float v[8]; };

__device__ __forceinline__ F8 ldg_keep32(const float* p) {
    F8 r;
    asm volatile("ld.global.nc.L2::evict_last.v8.b32 {%0,%1,%2,%3,%4,%5,%6,%7}, [%8];"
                 : "=f"(r.v[0]), "=f"(r.v[1]), "=f"(r.v[2]), "=f"(r.v[3]),
                   "=f"(r.v[4]), "=f"(r.v[5]), "=f"(r.v[6]), "=f"(r.v[7])
                 : "l"(p));
    return r;
}

__global__ __launch_bounds__(256)
void idx2pixel_kernel(const float* __restrict__ coords,
                      const float* __restrict__ visible,
                      float* __restrict__ out,
                      int n)
{
    int t = blockIdx.x * blockDim.x + threadIdx.x;
    if (t >= n) return;

    float2 co = __ldcs(reinterpret_cast<const float2*>(coords) + t);

    // floor-mod (python semantics) then +1
    float c0 = fmodf(co.x - 1.0f, MODV); if (c0 < 0.0f) c0 += MODV; c0 += 1.0f;
    float c1 = fmodf(co.y - 1.0f, MODV); if (c1 < 0.0f) c1 += MODV; c1 += 1.0f;

    float f0 = floorf(c0), f1 = floorf(c1);
    float d0 = c0 - f0,   d1 = c1 - f1;
    int i0 = (int)f0, i1 = (int)f1;

    // visible[r][col] starts at (r*2048 + col)*8 floats.
    // Row r=i0: [top_left | bottom_left]  (cols i1, i1+1) = 64B contiguous
    // Row r=i0+1: [top_right | bottom_right]
    const float* rowA = visible + ((size_t)i0 * HW + i1) * CH;
    const float* rowB = rowA + (size_t)HW * CH;

    // Issue all 4 gathers before any compute (max MLP).
    F8 tlbl_lo = ldg_keep32(rowA);      // tl[0..3], tl[4..7]? no: tl ch0-7
    F8 tlbl_hi = ldg_keep32(rowA + 8);  // bl ch0-7
    F8 trbr_lo = ldg_keep32(rowB);      // tr ch0-7
    F8 trbr_hi = ldg_keep32(rowB + 8);  // br ch0-7

    const float* tl = tlbl_lo.v;
    const float* bl = tlbl_hi.v;
    const float* tr = trbr_lo.v;
    const float* br = trbr_hi.v;

    bool zero = (c0 > DIMF);   // reference checks only dim 0 (never true; exactness)
    float w0 = zero ? 0.0f : d0;
    float w1 = zero ? 0.0f : d1;

    float o[8];
    #pragma unroll
    for (int k = 0; k < 8; k++) {
        float mt = tr[k] + w0 * (tl[k] - tr[k]);
        float mb = br[k] + w0 * (bl[k] - br[k]);
        o[k] = mb + w1 * (mt - mb);
    }
    if (zero) {
        #pragma unroll
        for (int k = 0; k < 8; k++) o[k] = 0.0f;
    }

    float4* dst = reinterpret_cast<float4*>(out + (size_t)t * CH);
    __stcs(dst + 0, make_float4(o[0], o[1], o[2], o[3]));
    __stcs(dst + 1, make_float4(o[4], o[5], o[6], o[7]));
}

extern "C" void kernel_launch(void* const* d_in, const int* in_sizes, int n_in,
                              void* d_out, int out_size)
{
    const float* coords  = (const float*)d_in[0];   // (N, 2) float32
    const float* visible = (const float*)d_in[1];   // (2048, 2048, 8) float32
    float* out = (float*)d_out;                     // (N, 8) float32

    int n = in_sizes[0] / 2;
    int threads = 256;
    int blocks = (n + threads - 1) / threads;
    idx2pixel_kernel<<<blocks, threads>>>(coords, visible, out, n);
}